// round 13
// baseline (speedup 1.0000x reference)
#include <cuda_runtime.h>
#include <cstdint>

#define BB 16
#define HH 8
#define GG 1024
#define II 256
#define DD 64

typedef unsigned long long ull;

// scratch for q, k, v projections: [b][h][g][d]
__device__ float g_q[BB*HH*GG*DD];
__device__ float g_k[BB*HH*GG*DD];
__device__ float g_v[BB*HH*GG*DD];
// packed mask bits: g_mbits[row][w] bit c = mask[row][32w+c] != 0
__device__ uint32_t g_mbits[GG * 32];

// ---- common helpers -------------------------------------------------------
__device__ __forceinline__ float tf32_rn(float x) {
    uint32_t u;
    asm("cvt.rna.tf32.f32 %0, %1;" : "=r"(u) : "f"(x));
    return __uint_as_float(u);
}
__device__ __forceinline__ void mma8(float* c, const uint32_t* a,
                                     uint32_t b0, uint32_t b1) {
    asm volatile(
        "mma.sync.aligned.m16n8k8.row.col.f32.tf32.tf32.f32 "
        "{%0,%1,%2,%3}, {%4,%5,%6,%7}, {%8,%9}, {%0,%1,%2,%3};"
        : "+f"(c[0]), "+f"(c[1]), "+f"(c[2]), "+f"(c[3])
        : "r"(a[0]), "r"(a[1]), "r"(a[2]), "r"(a[3]), "r"(b0), "r"(b1));
}
__device__ __forceinline__ uint32_t smem_u32(const void* p) {
    uint32_t a;
    asm("{ .reg .u64 t; cvta.to.shared.u64 t, %1; cvt.u32.u64 %0, t; }"
        : "=r"(a) : "l"(p));
    return a;
}
__device__ __forceinline__ void cpa16(uint32_t dst, const void* src) {
    asm volatile("cp.async.cg.shared.global [%0], [%1], 16;"
                 :: "r"(dst), "l"(src));
}
#define CPA_COMMIT() asm volatile("cp.async.commit_group;" ::: "memory")
#define CPA_WAIT0()  asm volatile("cp.async.wait_group 0;" ::: "memory")

// ---------------------------------------------------------------------------
// Mask bit-pack: one uint32 per 32 mask ints
// ---------------------------------------------------------------------------
__global__ __launch_bounds__(256) void maskpack_kernel(const int* __restrict__ mask)
{
    int id = blockIdx.x * 256 + threadIdx.x;       // 0 .. 32767
    const int4* p = (const int4*)(mask + id * 32);
    uint32_t b = 0;
#pragma unroll
    for (int t = 0; t < 8; t++) {
        int4 v = p[t];
        b |= (v.x ? 1u : 0u) << (t * 4 + 0);
        b |= (v.y ? 1u : 0u) << (t * 4 + 1);
        b |= (v.z ? 1u : 0u) << (t * 4 + 2);
        b |= (v.w ? 1u : 0u) << (t * 4 + 3);
    }
    g_mbits[id] = b;
}

// ===========================================================================
// Projection via mma.sync tf32 (3-term): C[16384x64] = A[16384x256] @ W[h]
// CTA: 128 rows x 64 cols, 256 threads (8 warps x 16 rows). BK=32, 8 chunks,
// A double-buffered via cp.async (4 x 16B per thread); W^T staged by LDG+STS.
// ===========================================================================
#define PAS 36                      // A / Wt smem stride (words)
#define P_AB0 0                     // A buf0: 128*36 = 4608
#define P_AB1 4608
#define P_WT0 9216                  // Wt buf0: 64*36 = 2304
#define P_WT1 11520
#define P_SM_WORDS 13824            // 55296 bytes

__global__ __launch_bounds__(256) void proj_mma_kernel(
    const float* __restrict__ A,    // [16384, 256]
    const float* __restrict__ W_Q,
    const float* __restrict__ W_K,
    const float* __restrict__ W_V)
{
    extern __shared__ float sm[];
    const uint32_t smb = smem_u32(sm);

    const int which = blockIdx.z;
    const float* W = (which == 0) ? W_Q : (which == 1) ? W_K : W_V;
    float* outbuf  = (which == 0) ? g_q : (which == 1) ? g_k : g_v;

    const int hh = blockIdx.y;
    const int r0 = blockIdx.x * 128;
    const float* Wh = W + hh * II * DD;

    const int tid = threadIdx.x;
    const int w = tid >> 5;
    const int lane = tid & 31;
    const int lq = lane >> 2;
    const int lr = lane & 3;
    const int R = w * 16;

    // A chunk cp.async mapping: 128x32 words; 2 threads/row, 16 words each
    const int ar = tid >> 1;                 // row 0..127
    const int ac = (tid & 1) << 4;           // word col 0 or 16
    // W transpose mapping: kr = lane (0..31), c8 = warp*8 cols
    const int kr = lane;
    const int c8 = w * 8;

    const uint32_t abuf[2] = { smb + P_AB0 * 4, smb + P_AB1 * 4 };
    const int wtbuf[2] = { P_WT0, P_WT1 };

    float o[8][4];
#pragma unroll
    for (int nt = 0; nt < 8; nt++)
#pragma unroll
        for (int e = 0; e < 4; e++) o[nt][e] = 0.f;

    // ---- prolog: chunk 0 ----
    {
        const float* src = A + (size_t)(r0 + ar) * II + ac;
        uint32_t d = abuf[0] + (ar * PAS + ac) * 4;
        cpa16(d, src);
        cpa16(d + 16, src + 4);
        cpa16(d + 32, src + 8);
        cpa16(d + 48, src + 12);
        CPA_COMMIT();
        float4 w0 = *(const float4*)(Wh + kr * DD + c8);
        float4 w1 = *(const float4*)(Wh + kr * DD + c8 + 4);
        const float* wf0 = &w0.x; const float* wf1 = &w1.x;
#pragma unroll
        for (int e = 0; e < 4; e++) {
            sm[P_WT0 + (c8 + e) * PAS + kr] = wf0[e];
            sm[P_WT0 + (c8 + 4 + e) * PAS + kr] = wf1[e];
        }
    }

    for (int c = 0; c < 8; c++) {
        CPA_WAIT0();
        __syncthreads();
        if (c < 7) {
            const float* src = A + (size_t)(r0 + ar) * II + (c + 1) * 32 + ac;
            uint32_t d = abuf[(c + 1) & 1] + (ar * PAS + ac) * 4;
            cpa16(d, src);
            cpa16(d + 16, src + 4);
            cpa16(d + 32, src + 8);
            cpa16(d + 48, src + 12);
            CPA_COMMIT();
            int wb = wtbuf[(c + 1) & 1];
            float4 w0 = *(const float4*)(Wh + ((c + 1) * 32 + kr) * DD + c8);
            float4 w1 = *(const float4*)(Wh + ((c + 1) * 32 + kr) * DD + c8 + 4);
            const float* wf0 = &w0.x; const float* wf1 = &w1.x;
#pragma unroll
            for (int e = 0; e < 4; e++) {
                sm[wb + (c8 + e) * PAS + kr] = wf0[e];
                sm[wb + (c8 + 4 + e) * PAS + kr] = wf1[e];
            }
        }
        const int ab = (c & 1) ? P_AB1 : P_AB0;
        const int wb = wtbuf[c & 1];
#pragma unroll
        for (int sk = 0; sk < 4; sk++) {
            uint32_t ah[4], al[4];
#pragma unroll
            for (int e = 0; e < 4; e++) {
                int row = R + (e & 1) * 8 + lq;
                int col = sk * 8 + (e >> 1) * 4 + lr;
                float v = sm[ab + row * PAS + col];
                float h = tf32_rn(v);
                ah[e] = __float_as_uint(h);
                al[e] = __float_as_uint(v - h);
            }
#pragma unroll
            for (int nt = 0; nt < 8; nt++) {
                int wa = wb + (nt * 8 + lq) * PAS + sk * 8 + lr;
                float r0f = sm[wa], r1f = sm[wa + 4];
                float h0 = tf32_rn(r0f), h1 = tf32_rn(r1f);
                uint32_t wh0 = __float_as_uint(h0), wh1 = __float_as_uint(h1);
                uint32_t wl0 = __float_as_uint(r0f - h0), wl1 = __float_as_uint(r1f - h1);
                mma8(o[nt], ah, wh0, wh1);
                mma8(o[nt], ah, wl0, wl1);
                mma8(o[nt], al, wh0, wh1);
            }
        }
    }

    // ---- epilogue ----
    const int mr0 = r0 + R + lq;
    const int mr1 = mr0 + 8;
    int b0 = mr0 >> 10, g0 = mr0 & (GG - 1);
    int b1 = mr1 >> 10, g1 = mr1 & (GG - 1);
    float* o0 = outbuf + (((size_t)(b0 * HH + hh) * GG + g0) * DD);
    float* o1 = outbuf + (((size_t)(b1 * HH + hh) * GG + g1) * DD);
#pragma unroll
    for (int nt = 0; nt < 8; nt++) {
        *(float2*)&o0[nt * 8 + 2 * lr] = make_float2(o[nt][0], o[nt][1]);
        *(float2*)&o1[nt * 8 + 2 * lr] = make_float2(o[nt][2], o[nt][3]);
    }
}

// ===========================================================================
// mma.sync tf32 flash attention — raw K/V in SMEM, on-the-fly hi/lo split,
// cp.async double buffering, one __syncthreads per tile.
// ===========================================================================

// SMEM word offsets
#define SKB0 0                      // K raw buf0 : 64 x 68
#define SKB1 4352
#define SVB0 8704                   // V raw buf0 : 64 x 72
#define SVB1 13312
#define SP   17920                  // P (and Q staging) : 64 x 68
#define SMB  22272                  // mask bits: 64 x 32 uint32
#define SM_WORDS 24320              // 97280 bytes

#define KS 68
#define VS 72

__global__ __launch_bounds__(128) void attn_mma_kernel(float* __restrict__ out)
{
    extern __shared__ float sm[];
    uint32_t* smMB = (uint32_t*)&sm[SMB];
    const uint32_t smb = smem_u32(sm);

    const int q0  = blockIdx.x * 64;
    const int bh  = blockIdx.y;
    const int tid = threadIdx.x;
    const int w   = tid >> 5;
    const int lane = tid & 31;
    const int lq = lane >> 2;
    const int lr = lane & 3;
    const int R  = w * 16;
    const int mr0 = R + lq;
    const int mr1 = mr0 + 8;

    const float* qb = g_q + (size_t)bh * GG * DD;
    const float* kb = g_k + (size_t)bh * GG * DD;
    const float* vb = g_v + (size_t)bh * GG * DD;

    // ---- prefetch tile 0 (K,V raw) ----
    {
#pragma unroll
        for (int t = 0; t < 8; t++) {
            int id = tid + t * 128;
            int j  = id >> 4;
            int c4 = (id & 15) << 2;
            cpa16(smb + (SKB0 + j * KS + c4) * 4, kb + j * DD + c4);
            cpa16(smb + (SVB0 + j * VS + c4) * 4, vb + j * DD + c4);
        }
        CPA_COMMIT();
    }

    // ---- stage Q (scaled by 1/8) into P region, copy mask bits ----
#pragma unroll
    for (int t = 0; t < 8; t++) {
        int id = tid + t * 128;
        int r  = id >> 4;
        int c4 = (id & 15) << 2;
        float4 v = *(const float4*)(qb + (size_t)(q0 + r) * DD + c4);
        v.x *= 0.125f; v.y *= 0.125f; v.z *= 0.125f; v.w *= 0.125f;
        *(float4*)&sm[SP + r * KS + c4] = v;
    }
#pragma unroll
    for (int t = 0; t < 4; t++) {
        int id = tid + t * 128;
        ((uint4*)smMB)[id] = ((const uint4*)(g_mbits + q0 * 32))[id];
    }
    __syncthreads();

    // ---- Q fragments (persistent): hi/lo tf32 ----
    uint32_t qh[8][4], ql[8][4];
#pragma unroll
    for (int sk = 0; sk < 8; sk++)
#pragma unroll
        for (int e = 0; e < 4; e++) {
            int row = R + (e & 1) * 8 + lq;
            int col = sk * 8 + (e >> 1) * 4 + lr;
            float v = sm[SP + row * KS + col];
            float h = tf32_rn(v);
            qh[sk][e] = __float_as_uint(h);
            ql[sk][e] = __float_as_uint(v - h);
        }

    float o[8][4];
#pragma unroll
    for (int nt = 0; nt < 8; nt++)
#pragma unroll
        for (int e = 0; e < 4; e++) o[nt][e] = 0.f;
    float m0 = -1e30f, m1 = -1e30f, l0 = 0.f, l1 = 0.f;

    for (int kt = 0; kt < 16; kt++) {
        CPA_WAIT0();
        __syncthreads();            // tile kt ready; all warps past compute kt-1
        if (kt < 15) {
            const float* kbt = kb + (size_t)(kt + 1) * 64 * DD;
            const float* vbt = vb + (size_t)(kt + 1) * 64 * DD;
            uint32_t kB = smb + (((kt + 1) & 1) ? SKB1 : SKB0) * 4;
            uint32_t vB = smb + (((kt + 1) & 1) ? SVB1 : SVB0) * 4;
#pragma unroll
            for (int t = 0; t < 8; t++) {
                int id = tid + t * 128;
                int j  = id >> 4;
                int c4 = (id & 15) << 2;
                cpa16(kB + (j * KS + c4) * 4, kbt + j * DD + c4);
                cpa16(vB + (j * VS + c4) * 4, vbt + j * DD + c4);
            }
            CPA_COMMIT();
        }
        const int KB = (kt & 1) ? SKB1 : SKB0;
        const int VB = (kt & 1) ? SVB1 : SVB0;

        // ---- S = Q K^T (3-term tf32, split on the fly) ----
        float s[8][4];
#pragma unroll
        for (int nt = 0; nt < 8; nt++)
#pragma unroll
            for (int e = 0; e < 4; e++) s[nt][e] = 0.f;

#pragma unroll
        for (int sk = 0; sk < 8; sk++) {
#pragma unroll
            for (int nt = 0; nt < 8; nt++) {
                int ka = KB + (nt * 8 + lq) * KS + sk * 8 + lr;
                float r0f = sm[ka], r1f = sm[ka + 4];
                float h0 = tf32_rn(r0f), h1 = tf32_rn(r1f);
                uint32_t bh0 = __float_as_uint(h0), bh1 = __float_as_uint(h1);
                uint32_t bl0 = __float_as_uint(r0f - h0), bl1 = __float_as_uint(r1f - h1);
                mma8(s[nt], qh[sk], bh0, bh1);
                mma8(s[nt], qh[sk], bl0, bl1);
                mma8(s[nt], ql[sk], bh0, bh1);
            }
        }

        // ---- mask + online softmax ----
        uint32_t w00 = smMB[mr0 * 32 + 2 * kt], w01 = smMB[mr0 * 32 + 2 * kt + 1];
        uint32_t w10 = smMB[mr1 * 32 + 2 * kt], w11 = smMB[mr1 * 32 + 2 * kt + 1];

        float tm0 = -1e30f, tm1 = -1e30f;
#pragma unroll
        for (int nt = 0; nt < 8; nt++) {
            uint32_t wa = (nt < 4) ? w00 : w01;
            uint32_t wb2 = (nt < 4) ? w10 : w11;
            int sh = 8 * (nt & 3) + 2 * lr;
            uint32_t ma = (wa >> sh) & 3u;
            uint32_t mb = (wb2 >> sh) & 3u;
            s[nt][0] = (ma & 1u) ? -1e30f : s[nt][0];
            s[nt][1] = (ma & 2u) ? -1e30f : s[nt][1];
            s[nt][2] = (mb & 1u) ? -1e30f : s[nt][2];
            s[nt][3] = (mb & 2u) ? -1e30f : s[nt][3];
            tm0 = fmaxf(tm0, fmaxf(s[nt][0], s[nt][1]));
            tm1 = fmaxf(tm1, fmaxf(s[nt][2], s[nt][3]));
        }
        tm0 = fmaxf(tm0, __shfl_xor_sync(0xffffffffu, tm0, 1));
        tm0 = fmaxf(tm0, __shfl_xor_sync(0xffffffffu, tm0, 2));
        tm1 = fmaxf(tm1, __shfl_xor_sync(0xffffffffu, tm1, 1));
        tm1 = fmaxf(tm1, __shfl_xor_sync(0xffffffffu, tm1, 2));

        float mn0 = fmaxf(m0, tm0), mn1 = fmaxf(m1, tm1);
        float a0 = __expf(m0 - mn0), a1 = __expf(m1 - mn1);
        m0 = mn0; m1 = mn1;

        float rs0 = 0.f, rs1 = 0.f;
#pragma unroll
        for (int nt = 0; nt < 8; nt++) {
            float p0 = tf32_rn(__expf(s[nt][0] - mn0));
            float p1 = tf32_rn(__expf(s[nt][1] - mn0));
            float p2 = tf32_rn(__expf(s[nt][2] - mn1));
            float p3 = tf32_rn(__expf(s[nt][3] - mn1));
            rs0 += p0 + p1;
            rs1 += p2 + p3;
            *(float2*)&sm[SP + mr0 * KS + nt * 8 + 2 * lr] = make_float2(p0, p1);
            *(float2*)&sm[SP + mr1 * KS + nt * 8 + 2 * lr] = make_float2(p2, p3);
        }
        rs0 += __shfl_xor_sync(0xffffffffu, rs0, 1);
        rs0 += __shfl_xor_sync(0xffffffffu, rs0, 2);
        rs1 += __shfl_xor_sync(0xffffffffu, rs1, 1);
        rs1 += __shfl_xor_sync(0xffffffffu, rs1, 2);
        l0 = l0 * a0 + rs0;
        l1 = l1 * a1 + rs1;
#pragma unroll
        for (int nt = 0; nt < 8; nt++) {
            o[nt][0] *= a0; o[nt][1] *= a0;
            o[nt][2] *= a1; o[nt][3] *= a1;
        }
        __syncwarp();               // P visible warp-wide (own rows only)

        // ---- O += P V (2-term tf32, V split on the fly) ----
#pragma unroll
        for (int u = 0; u < 8; u++) {
            uint32_t pa[4];
            pa[0] = __float_as_uint(sm[SP + mr0 * KS + u * 8 + lr]);
            pa[1] = __float_as_uint(sm[SP + mr1 * KS + u * 8 + lr]);
            pa[2] = __float_as_uint(sm[SP + mr0 * KS + u * 8 + 4 + lr]);
            pa[3] = __float_as_uint(sm[SP + mr1 * KS + u * 8 + 4 + lr]);
#pragma unroll
            for (int nt = 0; nt < 8; nt++) {
                int va = VB + (u * 8 + lr) * VS + nt * 8 + lq;
                float v0 = sm[va], v1 = sm[va + 4 * VS];
                float h0 = tf32_rn(v0), h1 = tf32_rn(v1);
                uint32_t vh0 = __float_as_uint(h0), vh1 = __float_as_uint(h1);
                uint32_t vl0 = __float_as_uint(v0 - h0), vl1 = __float_as_uint(v1 - h1);
                mma8(o[nt], pa, vh0, vh1);
                mma8(o[nt], pa, vl0, vl1);
            }
        }
    }

    // ---- epilogue ----
    float i0 = 1.f / l0, i1 = 1.f / l1;
    float* ob = out + ((size_t)bh * GG + q0) * DD;
#pragma unroll
    for (int nt = 0; nt < 8; nt++) {
        *(float2*)&ob[(size_t)mr0 * DD + nt * 8 + 2 * lr] =
            make_float2(o[nt][0] * i0, o[nt][1] * i0);
        *(float2*)&ob[(size_t)mr1 * DD + nt * 8 + 2 * lr] =
            make_float2(o[nt][2] * i1, o[nt][3] * i1);
    }
}

// ---------------------------------------------------------------------------
extern "C" void kernel_launch(void* const* d_in, const int* in_sizes, int n_in,
                              void* d_out, int out_size)
{
    const float* h    = (const float*)d_in[0];
    const int*   mask = (const int*)  d_in[1];
    const float* W_Q  = (const float*)d_in[2];
    const float* W_K  = (const float*)d_in[3];
    const float* W_V  = (const float*)d_in[4];
    float* out = (float*)d_out;

    cudaFuncSetAttribute(proj_mma_kernel,
                         cudaFuncAttributeMaxDynamicSharedMemorySize,
                         P_SM_WORDS * 4);
    cudaFuncSetAttribute(attn_mma_kernel,
                         cudaFuncAttributeMaxDynamicSharedMemorySize,
                         SM_WORDS * 4);

    dim3 pgrid(128, 8, 3);
    proj_mma_kernel<<<pgrid, 256, P_SM_WORDS * 4>>>(h, W_Q, W_K, W_V);

    maskpack_kernel<<<128, 256>>>(mask);

    dim3 agrid(GG / 64, BB * HH);   // 16 x 128 = 2048 CTAs
    attn_mma_kernel<<<agrid, 128, SM_WORDS * 4>>>(out);
}

// round 15
// speedup vs baseline: 1.1090x; 1.1090x over previous
#include <cuda_runtime.h>
#include <cstdint>

#define BB 16
#define HH 8
#define GG 1024
#define II 256
#define DD 64

typedef unsigned long long ull;

// scratch for q, k, v projections: [b][h][g][d]
__device__ float g_q[BB*HH*GG*DD];
__device__ float g_k[BB*HH*GG*DD];
__device__ float g_v[BB*HH*GG*DD];
// packed mask bits: g_mbits[row][w] bit c = mask[row][32w+c] != 0
__device__ uint32_t g_mbits[GG * 32];

// ---- common helpers -------------------------------------------------------
__device__ __forceinline__ float tf32_rn(float x) {
    uint32_t u;
    asm("cvt.rna.tf32.f32 %0, %1;" : "=r"(u) : "f"(x));
    return __uint_as_float(u);
}
__device__ __forceinline__ void mma8(float* c, const uint32_t* a,
                                     uint32_t b0, uint32_t b1) {
    asm volatile(
        "mma.sync.aligned.m16n8k8.row.col.f32.tf32.tf32.f32 "
        "{%0,%1,%2,%3}, {%4,%5,%6,%7}, {%8,%9}, {%0,%1,%2,%3};"
        : "+f"(c[0]), "+f"(c[1]), "+f"(c[2]), "+f"(c[3])
        : "r"(a[0]), "r"(a[1]), "r"(a[2]), "r"(a[3]), "r"(b0), "r"(b1));
}
__device__ __forceinline__ void mma8f(float* c, const uint32_t* a, float2 b) {
    mma8(c, a, __float_as_uint(b.x), __float_as_uint(b.y));
}
__device__ __forceinline__ uint32_t smem_u32(const void* p) {
    uint32_t a;
    asm("{ .reg .u64 t; cvta.to.shared.u64 t, %1; cvt.u32.u64 %0, t; }"
        : "=r"(a) : "l"(p));
    return a;
}
__device__ __forceinline__ void cpa16(uint32_t dst, const void* src) {
    asm volatile("cp.async.cg.shared.global [%0], [%1], 16;"
                 :: "r"(dst), "l"(src));
}
#define CPA_COMMIT() asm volatile("cp.async.commit_group;" ::: "memory")
#define CPA_WAIT0()  asm volatile("cp.async.wait_group 0;" ::: "memory")

// ---------------------------------------------------------------------------
// Mask bit-pack
// ---------------------------------------------------------------------------
__global__ __launch_bounds__(256) void maskpack_kernel(const int* __restrict__ mask)
{
    int id = blockIdx.x * 256 + threadIdx.x;
    const int4* p = (const int4*)(mask + id * 32);
    uint32_t b = 0;
#pragma unroll
    for (int t = 0; t < 8; t++) {
        int4 v = p[t];
        b |= (v.x ? 1u : 0u) << (t * 4 + 0);
        b |= (v.y ? 1u : 0u) << (t * 4 + 1);
        b |= (v.z ? 1u : 0u) << (t * 4 + 2);
        b |= (v.w ? 1u : 0u) << (t * 4 + 3);
    }
    g_mbits[id] = b;
}

// ===========================================================================
// Projection via mma.sync tf32 (3-term). Pre-split Wt hi/lo, pair-interleaved
// (LDS.64 b-frags). A raw via cp.async, a-frags split in registers.
// ===========================================================================
#define PAS 36
#define P_AB0 0                     // A raw buf: 128*36 = 4608 words
#define P_AB1 4608
#define P_WH0 9216                  // Wt hi buf0: 64*40 = 2560
#define P_WL0 11776
#define P_WH1 14336
#define P_WL1 16896
#define P_SM_WORDS 19456            // 77824 bytes
#define WTS 40

__global__ __launch_bounds__(256) void proj_mma_kernel(
    const float* __restrict__ A,
    const float* __restrict__ W_Q,
    const float* __restrict__ W_K,
    const float* __restrict__ W_V)
{
    extern __shared__ float sm[];
    const uint32_t smb = smem_u32(sm);

    const int which = blockIdx.z;
    const float* W = (which == 0) ? W_Q : (which == 1) ? W_K : W_V;
    float* outbuf  = (which == 0) ? g_q : (which == 1) ? g_k : g_v;

    const int hh = blockIdx.y;
    const int r0 = blockIdx.x * 128;
    const float* Wh = W + hh * II * DD;

    const int tid = threadIdx.x;
    const int w = tid >> 5;
    const int lane = tid & 31;
    const int lq = lane >> 2;
    const int lr = lane & 3;
    const int R = w * 16;

    // A cp.async mapping: 2 threads/row, 16 words each
    const int ar = tid >> 1;
    const int ac = (tid & 1) << 4;
    // W transpose mapping: kr = k-in-chunk (lane), c8w = n base (warp*8)
    const int kr = lane;
    const int c8w = w * 8;
    const int kg = kr >> 3, krr = kr & 7;
    const int wpos = kg * 8 + ((krr < 4) ? 2 * krr : 2 * (krr - 4) + 1);

    const uint32_t abuf[2] = { smb + P_AB0 * 4, smb + P_AB1 * 4 };
    const int whb[2] = { P_WH0, P_WH1 };
    const int wlb[2] = { P_WL0, P_WL1 };

    float o[8][4];
#pragma unroll
    for (int nt = 0; nt < 8; nt++)
#pragma unroll
        for (int e = 0; e < 4; e++) o[nt][e] = 0.f;

    // ---- prolog: chunk 0 ----
    {
        const float* src = A + (size_t)(r0 + ar) * II + ac;
        uint32_t d = abuf[0] + (ar * PAS + ac) * 4;
        cpa16(d, src); cpa16(d + 16, src + 4);
        cpa16(d + 32, src + 8); cpa16(d + 48, src + 12);
        CPA_COMMIT();
        float4 w0 = *(const float4*)(Wh + kr * DD + c8w);
        float4 w1 = *(const float4*)(Wh + kr * DD + c8w + 4);
        const float* wf0 = &w0.x; const float* wf1 = &w1.x;
#pragma unroll
        for (int e = 0; e < 4; e++) {
            float v = wf0[e], h = tf32_rn(v);
            sm[P_WH0 + (c8w + e) * WTS + wpos] = h;
            sm[P_WL0 + (c8w + e) * WTS + wpos] = v - h;
            v = wf1[e]; h = tf32_rn(v);
            sm[P_WH0 + (c8w + 4 + e) * WTS + wpos] = h;
            sm[P_WL0 + (c8w + 4 + e) * WTS + wpos] = v - h;
        }
    }

    for (int c = 0; c < 8; c++) {
        CPA_WAIT0();
        __syncthreads();
        if (c < 7) {
            const float* src = A + (size_t)(r0 + ar) * II + (c + 1) * 32 + ac;
            uint32_t d = abuf[(c + 1) & 1] + (ar * PAS + ac) * 4;
            cpa16(d, src); cpa16(d + 16, src + 4);
            cpa16(d + 32, src + 8); cpa16(d + 48, src + 12);
            CPA_COMMIT();
            int WHn = whb[(c + 1) & 1], WLn = wlb[(c + 1) & 1];
            float4 w0 = *(const float4*)(Wh + ((c + 1) * 32 + kr) * DD + c8w);
            float4 w1 = *(const float4*)(Wh + ((c + 1) * 32 + kr) * DD + c8w + 4);
            const float* wf0 = &w0.x; const float* wf1 = &w1.x;
#pragma unroll
            for (int e = 0; e < 4; e++) {
                float v = wf0[e], h = tf32_rn(v);
                sm[WHn + (c8w + e) * WTS + wpos] = h;
                sm[WLn + (c8w + e) * WTS + wpos] = v - h;
                v = wf1[e]; h = tf32_rn(v);
                sm[WHn + (c8w + 4 + e) * WTS + wpos] = h;
                sm[WLn + (c8w + 4 + e) * WTS + wpos] = v - h;
            }
        }
        const int ab = (c & 1) ? P_AB1 : P_AB0;
        const int WHc = whb[c & 1], WLc = wlb[c & 1];
#pragma unroll
        for (int sk = 0; sk < 4; sk++) {
            uint32_t ah[4], al[4];
#pragma unroll
            for (int e = 0; e < 4; e++) {
                int row = R + (e & 1) * 8 + lq;
                int col = sk * 8 + (e >> 1) * 4 + lr;
                float v = sm[ab + row * PAS + col];
                float h = tf32_rn(v);
                ah[e] = __float_as_uint(h);
                al[e] = __float_as_uint(v - h);
            }
#pragma unroll
            for (int nt = 0; nt < 8; nt++) {
                int wa = (nt * 8 + lq) * WTS + sk * 8 + 2 * lr;
                float2 wh2 = *(const float2*)&sm[WHc + wa];
                float2 wl2 = *(const float2*)&sm[WLc + wa];
                mma8f(o[nt], ah, wh2);
                mma8f(o[nt], ah, wl2);
                mma8f(o[nt], al, wh2);
            }
        }
    }

    // ---- epilogue ----
    const int mr0 = r0 + R + lq;
    const int mr1 = mr0 + 8;
    int b0 = mr0 >> 10, g0 = mr0 & (GG - 1);
    int b1 = mr1 >> 10, g1 = mr1 & (GG - 1);
    float* o0 = outbuf + (((size_t)(b0 * HH + hh) * GG + g0) * DD);
    float* o1 = outbuf + (((size_t)(b1 * HH + hh) * GG + g1) * DD);
#pragma unroll
    for (int nt = 0; nt < 8; nt++) {
        *(float2*)&o0[nt * 8 + 2 * lr] = make_float2(o[nt][0], o[nt][1]);
        *(float2*)&o1[nt * 8 + 2 * lr] = make_float2(o[nt][2], o[nt][3]);
    }
}

// ===========================================================================
// mma.sync tf32 flash attention — pre-split hi/lo smem (R11 model), K buffers
// pair-interleaved (LDS.64 b-frags), V as in R11.
// ===========================================================================
#define AKH 0                       // K hi: 64*72 = 4608
#define AKL 4608
#define AVH 9216                    // V hi: 64*72
#define AVL 13824
#define ASP 18432                   // P / Q staging: 64*68 = 4352
#define AMB 22784                   // mask bits: 2048
#define A_SM_WORDS 24832            // 99328 bytes
#define AKS 72
#define AVS 72
#define APS 68

__global__ __launch_bounds__(128) void attn_mma_kernel(float* __restrict__ out)
{
    extern __shared__ float sm[];
    uint32_t* smMB = (uint32_t*)&sm[AMB];

    const int q0  = blockIdx.x * 64;
    const int bh  = blockIdx.y;
    const int tid = threadIdx.x;
    const int w   = tid >> 5;
    const int lane = tid & 31;
    const int lq = lane >> 2;
    const int lr = lane & 3;
    const int R  = w * 16;
    const int mr0 = R + lq;
    const int mr1 = mr0 + 8;

    const float* qb = g_q + (size_t)bh * GG * DD;
    const float* kb = g_k + (size_t)bh * GG * DD;
    const float* vb = g_v + (size_t)bh * GG * DD;

    // ---- stage Q (scaled) into P region, copy mask bits ----
#pragma unroll
    for (int t = 0; t < 8; t++) {
        int id = tid + t * 128;
        int r  = id >> 4;
        int c4 = (id & 15) << 2;
        float4 v = *(const float4*)(qb + (size_t)(q0 + r) * DD + c4);
        v.x *= 0.125f; v.y *= 0.125f; v.z *= 0.125f; v.w *= 0.125f;
        *(float4*)&sm[ASP + r * APS + c4] = v;
    }
#pragma unroll
    for (int t = 0; t < 4; t++) {
        int id = tid + t * 128;
        ((uint4*)smMB)[id] = ((const uint4*)(g_mbits + q0 * 32))[id];
    }
    __syncthreads();

    // ---- Q fragments (persistent) hi/lo ----
    uint32_t qh[8][4], ql[8][4];
#pragma unroll
    for (int sk = 0; sk < 8; sk++)
#pragma unroll
        for (int e = 0; e < 4; e++) {
            int row = R + (e & 1) * 8 + lq;
            int col = sk * 8 + (e >> 1) * 4 + lr;
            float v = sm[ASP + row * APS + col];
            float h = tf32_rn(v);
            qh[sk][e] = __float_as_uint(h);
            ql[sk][e] = __float_as_uint(v - h);
        }

    float o[8][4];
#pragma unroll
    for (int nt = 0; nt < 8; nt++)
#pragma unroll
        for (int e = 0; e < 4; e++) o[nt][e] = 0.f;
    float m0 = -1e30f, m1 = -1e30f, l0 = 0.f, l1 = 0.f;

    for (int kt = 0; kt < 16; kt++) {
        __syncthreads();            // buffers free (prior compute done)
        const float* kbt = kb + (size_t)kt * 64 * DD;
        const float* vbt = vb + (size_t)kt * 64 * DD;
        // K: split + pair-interleave (d, d+4); 4 units of 8 d's per thread
#pragma unroll
        for (int t = 0; t < 4; t++) {
            int u  = tid + t * 128;          // 0..511
            int j  = u >> 3;
            int c8 = (u & 7) * 8;
            float4 x0 = *(const float4*)(kbt + j * DD + c8);
            float4 x1 = *(const float4*)(kbt + j * DD + c8 + 4);
            float h0 = tf32_rn(x0.x), h1 = tf32_rn(x0.y),
                  h2 = tf32_rn(x0.z), h3 = tf32_rn(x0.w);
            float h4 = tf32_rn(x1.x), h5 = tf32_rn(x1.y),
                  h6 = tf32_rn(x1.z), h7 = tf32_rn(x1.w);
            int ba = AKH + j * AKS + c8;
            *(float4*)&sm[ba]     = make_float4(h0, h4, h1, h5);
            *(float4*)&sm[ba + 4] = make_float4(h2, h6, h3, h7);
            ba = AKL + j * AKS + c8;
            *(float4*)&sm[ba]     = make_float4(x0.x - h0, x1.x - h4,
                                                x0.y - h1, x1.y - h5);
            *(float4*)&sm[ba + 4] = make_float4(x0.z - h2, x1.z - h6,
                                                x0.w - h3, x1.w - h7);
        }
        // V: split, natural layout (R11)
#pragma unroll
        for (int t = 0; t < 8; t++) {
            int id = tid + t * 128;
            int j  = id >> 4;
            int c4 = (id & 15) << 2;
            float4 vv = *(const float4*)(vbt + j * DD + c4);
            float4 h = make_float4(tf32_rn(vv.x), tf32_rn(vv.y),
                                   tf32_rn(vv.z), tf32_rn(vv.w));
            *(float4*)&sm[AVH + j * AVS + c4] = h;
            *(float4*)&sm[AVL + j * AVS + c4] =
                make_float4(vv.x - h.x, vv.y - h.y, vv.z - h.z, vv.w - h.w);
        }
        __syncthreads();

        // ---- S = Q K^T (3-term tf32, LDS.64 b-frags) ----
        float s[8][4];
#pragma unroll
        for (int nt = 0; nt < 8; nt++)
#pragma unroll
            for (int e = 0; e < 4; e++) s[nt][e] = 0.f;

#pragma unroll
        for (int sk = 0; sk < 8; sk++) {
#pragma unroll
            for (int nt = 0; nt < 8; nt++) {
                int ka = (nt * 8 + lq) * AKS + sk * 8 + 2 * lr;
                float2 bh2 = *(const float2*)&sm[AKH + ka];
                float2 bl2 = *(const float2*)&sm[AKL + ka];
                mma8f(s[nt], qh[sk], bh2);
                mma8f(s[nt], qh[sk], bl2);
                mma8f(s[nt], ql[sk], bh2);
            }
        }

        // ---- mask + online softmax ----
        uint32_t w00 = smMB[mr0 * 32 + 2 * kt], w01 = smMB[mr0 * 32 + 2 * kt + 1];
        uint32_t w10 = smMB[mr1 * 32 + 2 * kt], w11 = smMB[mr1 * 32 + 2 * kt + 1];

        float tm0 = -1e30f, tm1 = -1e30f;
#pragma unroll
        for (int nt = 0; nt < 8; nt++) {
            uint32_t wa = (nt < 4) ? w00 : w01;
            uint32_t wb2 = (nt < 4) ? w10 : w11;
            int sh = 8 * (nt & 3) + 2 * lr;
            uint32_t ma = (wa >> sh) & 3u;
            uint32_t mb = (wb2 >> sh) & 3u;
            s[nt][0] = (ma & 1u) ? -1e30f : s[nt][0];
            s[nt][1] = (ma & 2u) ? -1e30f : s[nt][1];
            s[nt][2] = (mb & 1u) ? -1e30f : s[nt][2];
            s[nt][3] = (mb & 2u) ? -1e30f : s[nt][3];
            tm0 = fmaxf(tm0, fmaxf(s[nt][0], s[nt][1]));
            tm1 = fmaxf(tm1, fmaxf(s[nt][2], s[nt][3]));
        }
        tm0 = fmaxf(tm0, __shfl_xor_sync(0xffffffffu, tm0, 1));
        tm0 = fmaxf(tm0, __shfl_xor_sync(0xffffffffu, tm0, 2));
        tm1 = fmaxf(tm1, __shfl_xor_sync(0xffffffffu, tm1, 1));
        tm1 = fmaxf(tm1, __shfl_xor_sync(0xffffffffu, tm1, 2));

        float mn0 = fmaxf(m0, tm0), mn1 = fmaxf(m1, tm1);
        float a0 = __expf(m0 - mn0), a1 = __expf(m1 - mn1);
        m0 = mn0; m1 = mn1;

        float rs0 = 0.f, rs1 = 0.f;
#pragma unroll
        for (int nt = 0; nt < 8; nt++) {
            float p0 = tf32_rn(__expf(s[nt][0] - mn0));
            float p1 = tf32_rn(__expf(s[nt][1] - mn0));
            float p2 = tf32_rn(__expf(s[nt][2] - mn1));
            float p3 = tf32_rn(__expf(s[nt][3] - mn1));
            rs0 += p0 + p1;
            rs1 += p2 + p3;
            *(float2*)&sm[ASP + mr0 * APS + nt * 8 + 2 * lr] = make_float2(p0, p1);
            *(float2*)&sm[ASP + mr1 * APS + nt * 8 + 2 * lr] = make_float2(p2, p3);
        }
        rs0 += __shfl_xor_sync(0xffffffffu, rs0, 1);
        rs0 += __shfl_xor_sync(0xffffffffu, rs0, 2);
        rs1 += __shfl_xor_sync(0xffffffffu, rs1, 1);
        rs1 += __shfl_xor_sync(0xffffffffu, rs1, 2);
        l0 = l0 * a0 + rs0;
        l1 = l1 * a1 + rs1;
#pragma unroll
        for (int nt = 0; nt < 8; nt++) {
            o[nt][0] *= a0; o[nt][1] *= a0;
            o[nt][2] *= a1; o[nt][3] *= a1;
        }
        __syncwarp();

        // ---- O += P V (2-term tf32) ----
#pragma unroll
        for (int u = 0; u < 8; u++) {
            uint32_t pa[4];
            pa[0] = __float_as_uint(sm[ASP + mr0 * APS + u * 8 + lr]);
            pa[1] = __float_as_uint(sm[ASP + mr1 * APS + u * 8 + lr]);
            pa[2] = __float_as_uint(sm[ASP + mr0 * APS + u * 8 + 4 + lr]);
            pa[3] = __float_as_uint(sm[ASP + mr1 * APS + u * 8 + 4 + lr]);
#pragma unroll
            for (int nt = 0; nt < 8; nt++) {
                int va = (u * 8 + lr) * AVS + nt * 8 + lq;
                uint32_t vh0 = __float_as_uint(sm[AVH + va]);
                uint32_t vh1 = __float_as_uint(sm[AVH + va + 4 * AVS]);
                uint32_t vl0 = __float_as_uint(sm[AVL + va]);
                uint32_t vl1 = __float_as_uint(sm[AVL + va + 4 * AVS]);
                mma8(o[nt], pa, vh0, vh1);
                mma8(o[nt], pa, vl0, vl1);
            }
        }
    }

    // ---- epilogue ----
    float i0 = 1.f / l0, i1 = 1.f / l1;
    float* ob = out + ((size_t)bh * GG + q0) * DD;
#pragma unroll
    for (int nt = 0; nt < 8; nt++) {
        *(float2*)&ob[(size_t)mr0 * DD + nt * 8 + 2 * lr] =
            make_float2(o[nt][0] * i0, o[nt][1] * i0);
        *(float2*)&ob[(size_t)mr1 * DD + nt * 8 + 2 * lr] =
            make_float2(o[nt][2] * i1, o[nt][3] * i1);
    }
}

// ---------------------------------------------------------------------------
extern "C" void kernel_launch(void* const* d_in, const int* in_sizes, int n_in,
                              void* d_out, int out_size)
{
    const float* h    = (const float*)d_in[0];
    const int*   mask = (const int*)  d_in[1];
    const float* W_Q  = (const float*)d_in[2];
    const float* W_K  = (const float*)d_in[3];
    const float* W_V  = (const float*)d_in[4];
    float* out = (float*)d_out;

    cudaFuncSetAttribute(proj_mma_kernel,
                         cudaFuncAttributeMaxDynamicSharedMemorySize,
                         P_SM_WORDS * 4);
    cudaFuncSetAttribute(attn_mma_kernel,
                         cudaFuncAttributeMaxDynamicSharedMemorySize,
                         A_SM_WORDS * 4);

    dim3 pgrid(128, 8, 3);
    proj_mma_kernel<<<pgrid, 256, P_SM_WORDS * 4>>>(h, W_Q, W_K, W_V);

    maskpack_kernel<<<128, 256>>>(mask);

    dim3 agrid(GG / 64, BB * HH);
    attn_mma_kernel<<<agrid, 128, A_SM_WORDS * 4>>>(out);
}

// round 16
// speedup vs baseline: 1.2292x; 1.1083x over previous
#include <cuda_runtime.h>
#include <cstdint>

#define BB 16
#define HH 8
#define GG 1024
#define II 256
#define DD 64

typedef unsigned long long ull;

__device__ float g_q[BB*HH*GG*DD];
__device__ float g_k[BB*HH*GG*DD];
__device__ float g_v[BB*HH*GG*DD];
__device__ uint32_t g_mbits[GG * 32];

// ---- common helpers -------------------------------------------------------
__device__ __forceinline__ float tf32_rn(float x) {
    uint32_t u;
    asm("cvt.rna.tf32.f32 %0, %1;" : "=r"(u) : "f"(x));
    return __uint_as_float(u);
}
__device__ __forceinline__ void mma8(float* c, const uint32_t* a,
                                     uint32_t b0, uint32_t b1) {
    asm volatile(
        "mma.sync.aligned.m16n8k8.row.col.f32.tf32.tf32.f32 "
        "{%0,%1,%2,%3}, {%4,%5,%6,%7}, {%8,%9}, {%0,%1,%2,%3};"
        : "+f"(c[0]), "+f"(c[1]), "+f"(c[2]), "+f"(c[3])
        : "r"(a[0]), "r"(a[1]), "r"(a[2]), "r"(a[3]), "r"(b0), "r"(b1));
}
__device__ __forceinline__ void mma8f(float* c, const uint32_t* a, float2 b) {
    mma8(c, a, __float_as_uint(b.x), __float_as_uint(b.y));
}
__device__ __forceinline__ uint32_t smem_u32(const void* p) {
    uint32_t a;
    asm("{ .reg .u64 t; cvta.to.shared.u64 t, %1; cvt.u32.u64 %0, t; }"
        : "=r"(a) : "l"(p));
    return a;
}
__device__ __forceinline__ void cpa16(uint32_t dst, const void* src) {
    asm volatile("cp.async.cg.shared.global [%0], [%1], 16;"
                 :: "r"(dst), "l"(src));
}
#define CPA_COMMIT() asm volatile("cp.async.commit_group;" ::: "memory")
#define CPA_WAIT0()  asm volatile("cp.async.wait_group 0;" ::: "memory")

// ---------------------------------------------------------------------------
// Mask bit-pack
// ---------------------------------------------------------------------------
__global__ __launch_bounds__(256) void maskpack_kernel(const int* __restrict__ mask)
{
    int id = blockIdx.x * 256 + threadIdx.x;
    const int4* p = (const int4*)(mask + id * 32);
    uint32_t b = 0;
#pragma unroll
    for (int t = 0; t < 8; t++) {
        int4 v = p[t];
        b |= (v.x ? 1u : 0u) << (t * 4 + 0);
        b |= (v.y ? 1u : 0u) << (t * 4 + 1);
        b |= (v.z ? 1u : 0u) << (t * 4 + 2);
        b |= (v.w ? 1u : 0u) << (t * 4 + 3);
    }
    g_mbits[id] = b;
}

// ===========================================================================
// Projection via mma.sync tf32. Q,K: 3-term; V: 2-term (V tolerance ~1e-3).
// Pre-split Wt hi/lo pair-interleaved (LDS.64 b-frags); A raw via cp.async.
// ===========================================================================
#define PAS 36
#define P_AB0 0
#define P_AB1 4608
#define P_WH0 9216
#define P_WL0 11776
#define P_WH1 14336
#define P_WL1 16896
#define P_SM_WORDS 19456
#define WTS 40

__global__ __launch_bounds__(256) void proj_mma_kernel(
    const float* __restrict__ A,
    const float* __restrict__ W_Q,
    const float* __restrict__ W_K,
    const float* __restrict__ W_V)
{
    extern __shared__ float sm[];
    const uint32_t smb = smem_u32(sm);

    const int which = blockIdx.z;
    const float* W = (which == 0) ? W_Q : (which == 1) ? W_K : W_V;
    float* outbuf  = (which == 0) ? g_q : (which == 1) ? g_k : g_v;
    const bool third = (which != 2);

    const int hh = blockIdx.y;
    const int r0 = blockIdx.x * 128;
    const float* Wh = W + hh * II * DD;

    const int tid = threadIdx.x;
    const int w = tid >> 5;
    const int lane = tid & 31;
    const int lq = lane >> 2;
    const int lr = lane & 3;
    const int R = w * 16;

    const int ar = tid >> 1;
    const int ac = (tid & 1) << 4;
    const int kr = lane;
    const int c8w = w * 8;
    const int kg = kr >> 3, krr = kr & 7;
    const int wpos = kg * 8 + ((krr < 4) ? 2 * krr : 2 * (krr - 4) + 1);

    const uint32_t abuf[2] = { smb + P_AB0 * 4, smb + P_AB1 * 4 };
    const int whb[2] = { P_WH0, P_WH1 };
    const int wlb[2] = { P_WL0, P_WL1 };

    float o[8][4];
#pragma unroll
    for (int nt = 0; nt < 8; nt++)
#pragma unroll
        for (int e = 0; e < 4; e++) o[nt][e] = 0.f;

    // ---- prolog: chunk 0 ----
    {
        const float* src = A + (size_t)(r0 + ar) * II + ac;
        uint32_t d = abuf[0] + (ar * PAS + ac) * 4;
        cpa16(d, src); cpa16(d + 16, src + 4);
        cpa16(d + 32, src + 8); cpa16(d + 48, src + 12);
        CPA_COMMIT();
        float4 w0 = *(const float4*)(Wh + kr * DD + c8w);
        float4 w1 = *(const float4*)(Wh + kr * DD + c8w + 4);
        const float* wf0 = &w0.x; const float* wf1 = &w1.x;
#pragma unroll
        for (int e = 0; e < 4; e++) {
            float v = wf0[e], h = tf32_rn(v);
            sm[P_WH0 + (c8w + e) * WTS + wpos] = h;
            sm[P_WL0 + (c8w + e) * WTS + wpos] = v - h;
            v = wf1[e]; h = tf32_rn(v);
            sm[P_WH0 + (c8w + 4 + e) * WTS + wpos] = h;
            sm[P_WL0 + (c8w + 4 + e) * WTS + wpos] = v - h;
        }
    }

    for (int c = 0; c < 8; c++) {
        CPA_WAIT0();
        __syncthreads();
        if (c < 7) {
            const float* src = A + (size_t)(r0 + ar) * II + (c + 1) * 32 + ac;
            uint32_t d = abuf[(c + 1) & 1] + (ar * PAS + ac) * 4;
            cpa16(d, src); cpa16(d + 16, src + 4);
            cpa16(d + 32, src + 8); cpa16(d + 48, src + 12);
            CPA_COMMIT();
            int WHn = whb[(c + 1) & 1], WLn = wlb[(c + 1) & 1];
            float4 w0 = *(const float4*)(Wh + ((c + 1) * 32 + kr) * DD + c8w);
            float4 w1 = *(const float4*)(Wh + ((c + 1) * 32 + kr) * DD + c8w + 4);
            const float* wf0 = &w0.x; const float* wf1 = &w1.x;
#pragma unroll
            for (int e = 0; e < 4; e++) {
                float v = wf0[e], h = tf32_rn(v);
                sm[WHn + (c8w + e) * WTS + wpos] = h;
                sm[WLn + (c8w + e) * WTS + wpos] = v - h;
                v = wf1[e]; h = tf32_rn(v);
                sm[WHn + (c8w + 4 + e) * WTS + wpos] = h;
                sm[WLn + (c8w + 4 + e) * WTS + wpos] = v - h;
            }
        }
        const int ab = (c & 1) ? P_AB1 : P_AB0;
        const int WHc = whb[c & 1], WLc = wlb[c & 1];
#pragma unroll
        for (int sk = 0; sk < 4; sk++) {
            uint32_t ah[4], al[4];
#pragma unroll
            for (int e = 0; e < 4; e++) {
                int row = R + (e & 1) * 8 + lq;
                int col = sk * 8 + (e >> 1) * 4 + lr;
                float v = sm[ab + row * PAS + col];
                float h = tf32_rn(v);
                ah[e] = __float_as_uint(h);
                al[e] = __float_as_uint(v - h);
            }
#pragma unroll
            for (int nt = 0; nt < 8; nt++) {
                int wa = (nt * 8 + lq) * WTS + sk * 8 + 2 * lr;
                float2 wh2 = *(const float2*)&sm[WHc + wa];
                float2 wl2 = *(const float2*)&sm[WLc + wa];
                mma8f(o[nt], ah, wh2);
                mma8f(o[nt], ah, wl2);
                if (third) mma8f(o[nt], al, wh2);
            }
        }
    }

    // ---- epilogue ----
    const int mr0 = r0 + R + lq;
    const int mr1 = mr0 + 8;
    int b0 = mr0 >> 10, g0 = mr0 & (GG - 1);
    int b1 = mr1 >> 10, g1 = mr1 & (GG - 1);
    float* o0 = outbuf + (((size_t)(b0 * HH + hh) * GG + g0) * DD);
    float* o1 = outbuf + (((size_t)(b1 * HH + hh) * GG + g1) * DD);
#pragma unroll
    for (int nt = 0; nt < 8; nt++) {
        *(float2*)&o0[nt * 8 + 2 * lr] = make_float2(o[nt][0], o[nt][1]);
        *(float2*)&o1[nt * 8 + 2 * lr] = make_float2(o[nt][2], o[nt][3]);
    }
}

// ===========================================================================
// mma.sync tf32 flash attention — 3-term S, SINGLE-term PV (V rounded to
// tf32; P already tf32 with l summed over rounded P so it cancels).
// ===========================================================================
#define AKH 0                       // K hi: 64*72 = 4608
#define AKL 4608                    // K lo
#define AVH 9216                    // V hi: 64*72
#define ASP 13824                   // P / Q staging: 64*68 = 4352
#define AMB 18176                   // mask bits: 2048
#define A_SM_WORDS 20224            // 80896 bytes
#define AKS 72
#define AVS 72
#define APS 68

__global__ __launch_bounds__(128) void attn_mma_kernel(float* __restrict__ out)
{
    extern __shared__ float sm[];
    uint32_t* smMB = (uint32_t*)&sm[AMB];

    const int q0  = blockIdx.x * 64;
    const int bh  = blockIdx.y;
    const int tid = threadIdx.x;
    const int w   = tid >> 5;
    const int lane = tid & 31;
    const int lq = lane >> 2;
    const int lr = lane & 3;
    const int R  = w * 16;
    const int mr0 = R + lq;
    const int mr1 = mr0 + 8;

    const float* qb = g_q + (size_t)bh * GG * DD;
    const float* kb = g_k + (size_t)bh * GG * DD;
    const float* vb = g_v + (size_t)bh * GG * DD;

    // ---- stage Q (scaled) into P region, copy mask bits ----
#pragma unroll
    for (int t = 0; t < 8; t++) {
        int id = tid + t * 128;
        int r  = id >> 4;
        int c4 = (id & 15) << 2;
        float4 v = *(const float4*)(qb + (size_t)(q0 + r) * DD + c4);
        v.x *= 0.125f; v.y *= 0.125f; v.z *= 0.125f; v.w *= 0.125f;
        *(float4*)&sm[ASP + r * APS + c4] = v;
    }
#pragma unroll
    for (int t = 0; t < 4; t++) {
        int id = tid + t * 128;
        ((uint4*)smMB)[id] = ((const uint4*)(g_mbits + q0 * 32))[id];
    }
    __syncthreads();

    // ---- Q fragments (persistent) hi/lo ----
    uint32_t qh[8][4], ql[8][4];
#pragma unroll
    for (int sk = 0; sk < 8; sk++)
#pragma unroll
        for (int e = 0; e < 4; e++) {
            int row = R + (e & 1) * 8 + lq;
            int col = sk * 8 + (e >> 1) * 4 + lr;
            float v = sm[ASP + row * APS + col];
            float h = tf32_rn(v);
            qh[sk][e] = __float_as_uint(h);
            ql[sk][e] = __float_as_uint(v - h);
        }

    float o[8][4];
#pragma unroll
    for (int nt = 0; nt < 8; nt++)
#pragma unroll
        for (int e = 0; e < 4; e++) o[nt][e] = 0.f;
    float m0 = -1e30f, m1 = -1e30f, l0 = 0.f, l1 = 0.f;

    for (int kt = 0; kt < 16; kt++) {
        __syncthreads();
        const float* kbt = kb + (size_t)kt * 64 * DD;
        const float* vbt = vb + (size_t)kt * 64 * DD;
        // K: split + pair-interleave (d, d+4)
#pragma unroll
        for (int t = 0; t < 4; t++) {
            int u  = tid + t * 128;
            int j  = u >> 3;
            int c8 = (u & 7) * 8;
            float4 x0 = *(const float4*)(kbt + j * DD + c8);
            float4 x1 = *(const float4*)(kbt + j * DD + c8 + 4);
            float h0 = tf32_rn(x0.x), h1 = tf32_rn(x0.y),
                  h2 = tf32_rn(x0.z), h3 = tf32_rn(x0.w);
            float h4 = tf32_rn(x1.x), h5 = tf32_rn(x1.y),
                  h6 = tf32_rn(x1.z), h7 = tf32_rn(x1.w);
            int ba = AKH + j * AKS + c8;
            *(float4*)&sm[ba]     = make_float4(h0, h4, h1, h5);
            *(float4*)&sm[ba + 4] = make_float4(h2, h6, h3, h7);
            ba = AKL + j * AKS + c8;
            *(float4*)&sm[ba]     = make_float4(x0.x - h0, x1.x - h4,
                                                x0.y - h1, x1.y - h5);
            *(float4*)&sm[ba + 4] = make_float4(x0.z - h2, x1.z - h6,
                                                x0.w - h3, x1.w - h7);
        }
        // V: tf32 hi only, natural layout
#pragma unroll
        for (int t = 0; t < 8; t++) {
            int id = tid + t * 128;
            int j  = id >> 4;
            int c4 = (id & 15) << 2;
            float4 vv = *(const float4*)(vbt + j * DD + c4);
            *(float4*)&sm[AVH + j * AVS + c4] =
                make_float4(tf32_rn(vv.x), tf32_rn(vv.y),
                            tf32_rn(vv.z), tf32_rn(vv.w));
        }
        __syncthreads();

        // ---- S = Q K^T (3-term tf32, LDS.64 b-frags) ----
        float s[8][4];
#pragma unroll
        for (int nt = 0; nt < 8; nt++)
#pragma unroll
            for (int e = 0; e < 4; e++) s[nt][e] = 0.f;

#pragma unroll
        for (int sk = 0; sk < 8; sk++) {
#pragma unroll
            for (int nt = 0; nt < 8; nt++) {
                int ka = (nt * 8 + lq) * AKS + sk * 8 + 2 * lr;
                float2 bh2 = *(const float2*)&sm[AKH + ka];
                float2 bl2 = *(const float2*)&sm[AKL + ka];
                mma8f(s[nt], qh[sk], bh2);
                mma8f(s[nt], qh[sk], bl2);
                mma8f(s[nt], ql[sk], bh2);
            }
        }

        // ---- mask + online softmax ----
        uint32_t w00 = smMB[mr0 * 32 + 2 * kt], w01 = smMB[mr0 * 32 + 2 * kt + 1];
        uint32_t w10 = smMB[mr1 * 32 + 2 * kt], w11 = smMB[mr1 * 32 + 2 * kt + 1];

        float tm0 = -1e30f, tm1 = -1e30f;
#pragma unroll
        for (int nt = 0; nt < 8; nt++) {
            uint32_t wa = (nt < 4) ? w00 : w01;
            uint32_t wb2 = (nt < 4) ? w10 : w11;
            int sh = 8 * (nt & 3) + 2 * lr;
            uint32_t ma = (wa >> sh) & 3u;
            uint32_t mb = (wb2 >> sh) & 3u;
            s[nt][0] = (ma & 1u) ? -1e30f : s[nt][0];
            s[nt][1] = (ma & 2u) ? -1e30f : s[nt][1];
            s[nt][2] = (mb & 1u) ? -1e30f : s[nt][2];
            s[nt][3] = (mb & 2u) ? -1e30f : s[nt][3];
            tm0 = fmaxf(tm0, fmaxf(s[nt][0], s[nt][1]));
            tm1 = fmaxf(tm1, fmaxf(s[nt][2], s[nt][3]));
        }
        tm0 = fmaxf(tm0, __shfl_xor_sync(0xffffffffu, tm0, 1));
        tm0 = fmaxf(tm0, __shfl_xor_sync(0xffffffffu, tm0, 2));
        tm1 = fmaxf(tm1, __shfl_xor_sync(0xffffffffu, tm1, 1));
        tm1 = fmaxf(tm1, __shfl_xor_sync(0xffffffffu, tm1, 2));

        float mn0 = fmaxf(m0, tm0), mn1 = fmaxf(m1, tm1);
        float a0 = __expf(m0 - mn0), a1 = __expf(m1 - mn1);
        m0 = mn0; m1 = mn1;

        float rs0 = 0.f, rs1 = 0.f;
#pragma unroll
        for (int nt = 0; nt < 8; nt++) {
            float p0 = tf32_rn(__expf(s[nt][0] - mn0));
            float p1 = tf32_rn(__expf(s[nt][1] - mn0));
            float p2 = tf32_rn(__expf(s[nt][2] - mn1));
            float p3 = tf32_rn(__expf(s[nt][3] - mn1));
            rs0 += p0 + p1;
            rs1 += p2 + p3;
            *(float2*)&sm[ASP + mr0 * APS + nt * 8 + 2 * lr] = make_float2(p0, p1);
            *(float2*)&sm[ASP + mr1 * APS + nt * 8 + 2 * lr] = make_float2(p2, p3);
        }
        rs0 += __shfl_xor_sync(0xffffffffu, rs0, 1);
        rs0 += __shfl_xor_sync(0xffffffffu, rs0, 2);
        rs1 += __shfl_xor_sync(0xffffffffu, rs1, 1);
        rs1 += __shfl_xor_sync(0xffffffffu, rs1, 2);
        l0 = l0 * a0 + rs0;
        l1 = l1 * a1 + rs1;
#pragma unroll
        for (int nt = 0; nt < 8; nt++) {
            o[nt][0] *= a0; o[nt][1] *= a0;
            o[nt][2] *= a1; o[nt][3] *= a1;
        }
        __syncwarp();

        // ---- O += P V (single-term tf32) ----
#pragma unroll
        for (int u = 0; u < 8; u++) {
            uint32_t pa[4];
            pa[0] = __float_as_uint(sm[ASP + mr0 * APS + u * 8 + lr]);
            pa[1] = __float_as_uint(sm[ASP + mr1 * APS + u * 8 + lr]);
            pa[2] = __float_as_uint(sm[ASP + mr0 * APS + u * 8 + 4 + lr]);
            pa[3] = __float_as_uint(sm[ASP + mr1 * APS + u * 8 + 4 + lr]);
#pragma unroll
            for (int nt = 0; nt < 8; nt++) {
                int va = (u * 8 + lr) * AVS + nt * 8 + lq;
                uint32_t vh0 = __float_as_uint(sm[AVH + va]);
                uint32_t vh1 = __float_as_uint(sm[AVH + va + 4 * AVS]);
                mma8(o[nt], pa, vh0, vh1);
            }
        }
    }

    // ---- epilogue ----
    float i0 = 1.f / l0, i1 = 1.f / l1;
    float* ob = out + ((size_t)bh * GG + q0) * DD;
#pragma unroll
    for (int nt = 0; nt < 8; nt++) {
        *(float2*)&ob[(size_t)mr0 * DD + nt * 8 + 2 * lr] =
            make_float2(o[nt][0] * i0, o[nt][1] * i0);
        *(float2*)&ob[(size_t)mr1 * DD + nt * 8 + 2 * lr] =
            make_float2(o[nt][2] * i1, o[nt][3] * i1);
    }
}

// ---------------------------------------------------------------------------
extern "C" void kernel_launch(void* const* d_in, const int* in_sizes, int n_in,
                              void* d_out, int out_size)
{
    const float* h    = (const float*)d_in[0];
    const int*   mask = (const int*)  d_in[1];
    const float* W_Q  = (const float*)d_in[2];
    const float* W_K  = (const float*)d_in[3];
    const float* W_V  = (const float*)d_in[4];
    float* out = (float*)d_out;

    cudaFuncSetAttribute(proj_mma_kernel,
                         cudaFuncAttributeMaxDynamicSharedMemorySize,
                         P_SM_WORDS * 4);
    cudaFuncSetAttribute(attn_mma_kernel,
                         cudaFuncAttributeMaxDynamicSharedMemorySize,
                         A_SM_WORDS * 4);

    dim3 pgrid(128, 8, 3);
    proj_mma_kernel<<<pgrid, 256, P_SM_WORDS * 4>>>(h, W_Q, W_K, W_V);

    maskpack_kernel<<<128, 256>>>(mask);

    dim3 agrid(GG / 64, BB * HH);
    attn_mma_kernel<<<agrid, 128, A_SM_WORDS * 4>>>(out);
}

// round 17
// speedup vs baseline: 1.2565x; 1.0222x over previous
#include <cuda_runtime.h>
#include <cstdint>

#define BB 16
#define HH 8
#define GG 1024
#define II 256
#define DD 64

typedef unsigned long long ull;

__device__ float g_q[BB*HH*GG*DD];
__device__ float g_k[BB*HH*GG*DD];
__device__ float g_v[BB*HH*GG*DD];
__device__ uint32_t g_mbits[GG * 32];

// ---- common helpers -------------------------------------------------------
__device__ __forceinline__ float tf32_rn(float x) {
    uint32_t u;
    asm("cvt.rna.tf32.f32 %0, %1;" : "=r"(u) : "f"(x));
    return __uint_as_float(u);
}
__device__ __forceinline__ uint32_t bf2pack(float lo, float hi) {
    uint32_t r;
    asm("cvt.rn.bf16x2.f32 %0, %1, %2;" : "=r"(r) : "f"(hi), "f"(lo));
    return r;
}
__device__ __forceinline__ void mma8(float* c, const uint32_t* a,
                                     uint32_t b0, uint32_t b1) {
    asm volatile(
        "mma.sync.aligned.m16n8k8.row.col.f32.tf32.tf32.f32 "
        "{%0,%1,%2,%3}, {%4,%5,%6,%7}, {%8,%9}, {%0,%1,%2,%3};"
        : "+f"(c[0]), "+f"(c[1]), "+f"(c[2]), "+f"(c[3])
        : "r"(a[0]), "r"(a[1]), "r"(a[2]), "r"(a[3]), "r"(b0), "r"(b1));
}
__device__ __forceinline__ void mma8f(float* c, const uint32_t* a, float2 b) {
    mma8(c, a, __float_as_uint(b.x), __float_as_uint(b.y));
}
__device__ __forceinline__ void mma16b(float* c, const uint32_t* a,
                                       uint32_t b0, uint32_t b1) {
    asm volatile(
        "mma.sync.aligned.m16n8k16.row.col.f32.bf16.bf16.f32 "
        "{%0,%1,%2,%3}, {%4,%5,%6,%7}, {%8,%9}, {%0,%1,%2,%3};"
        : "+f"(c[0]), "+f"(c[1]), "+f"(c[2]), "+f"(c[3])
        : "r"(a[0]), "r"(a[1]), "r"(a[2]), "r"(a[3]), "r"(b0), "r"(b1));
}
__device__ __forceinline__ uint32_t smem_u32(const void* p) {
    uint32_t a;
    asm("{ .reg .u64 t; cvta.to.shared.u64 t, %1; cvt.u32.u64 %0, t; }"
        : "=r"(a) : "l"(p));
    return a;
}
__device__ __forceinline__ void cpa16(uint32_t dst, const void* src) {
    asm volatile("cp.async.cg.shared.global [%0], [%1], 16;"
                 :: "r"(dst), "l"(src));
}
#define CPA_COMMIT() asm volatile("cp.async.commit_group;" ::: "memory")
#define CPA_WAIT0()  asm volatile("cp.async.wait_group 0;" ::: "memory")

// ---------------------------------------------------------------------------
// Mask bit-pack
// ---------------------------------------------------------------------------
__global__ __launch_bounds__(256) void maskpack_kernel(const int* __restrict__ mask)
{
    int id = blockIdx.x * 256 + threadIdx.x;
    const int4* p = (const int4*)(mask + id * 32);
    uint32_t b = 0;
#pragma unroll
    for (int t = 0; t < 8; t++) {
        int4 v = p[t];
        b |= (v.x ? 1u : 0u) << (t * 4 + 0);
        b |= (v.y ? 1u : 0u) << (t * 4 + 1);
        b |= (v.z ? 1u : 0u) << (t * 4 + 2);
        b |= (v.w ? 1u : 0u) << (t * 4 + 3);
    }
    g_mbits[id] = b;
}

// ===========================================================================
// Projection via mma.sync tf32 (3-term, unchanged from R16 except V keeps
// third term — measured free, buys error margin).
// ===========================================================================
#define PAS 36
#define P_AB0 0
#define P_AB1 4608
#define P_WH0 9216
#define P_WL0 11776
#define P_WH1 14336
#define P_WL1 16896
#define P_SM_WORDS 19456
#define WTS 40

__global__ __launch_bounds__(256) void proj_mma_kernel(
    const float* __restrict__ A,
    const float* __restrict__ W_Q,
    const float* __restrict__ W_K,
    const float* __restrict__ W_V)
{
    extern __shared__ float sm[];
    const uint32_t smb = smem_u32(sm);

    const int which = blockIdx.z;
    const float* W = (which == 0) ? W_Q : (which == 1) ? W_K : W_V;
    float* outbuf  = (which == 0) ? g_q : (which == 1) ? g_k : g_v;

    const int hh = blockIdx.y;
    const int r0 = blockIdx.x * 128;
    const float* Wh = W + hh * II * DD;

    const int tid = threadIdx.x;
    const int w = tid >> 5;
    const int lane = tid & 31;
    const int lq = lane >> 2;
    const int lr = lane & 3;
    const int R = w * 16;

    const int ar = tid >> 1;
    const int ac = (tid & 1) << 4;
    const int kr = lane;
    const int c8w = w * 8;
    const int kg = kr >> 3, krr = kr & 7;
    const int wpos = kg * 8 + ((krr < 4) ? 2 * krr : 2 * (krr - 4) + 1);

    const uint32_t abuf[2] = { smb + P_AB0 * 4, smb + P_AB1 * 4 };
    const int whb[2] = { P_WH0, P_WH1 };
    const int wlb[2] = { P_WL0, P_WL1 };

    float o[8][4];
#pragma unroll
    for (int nt = 0; nt < 8; nt++)
#pragma unroll
        for (int e = 0; e < 4; e++) o[nt][e] = 0.f;

    // ---- prolog: chunk 0 ----
    {
        const float* src = A + (size_t)(r0 + ar) * II + ac;
        uint32_t d = abuf[0] + (ar * PAS + ac) * 4;
        cpa16(d, src); cpa16(d + 16, src + 4);
        cpa16(d + 32, src + 8); cpa16(d + 48, src + 12);
        CPA_COMMIT();
        float4 w0 = *(const float4*)(Wh + kr * DD + c8w);
        float4 w1 = *(const float4*)(Wh + kr * DD + c8w + 4);
        const float* wf0 = &w0.x; const float* wf1 = &w1.x;
#pragma unroll
        for (int e = 0; e < 4; e++) {
            float v = wf0[e], h = tf32_rn(v);
            sm[P_WH0 + (c8w + e) * WTS + wpos] = h;
            sm[P_WL0 + (c8w + e) * WTS + wpos] = v - h;
            v = wf1[e]; h = tf32_rn(v);
            sm[P_WH0 + (c8w + 4 + e) * WTS + wpos] = h;
            sm[P_WL0 + (c8w + 4 + e) * WTS + wpos] = v - h;
        }
    }

    for (int c = 0; c < 8; c++) {
        CPA_WAIT0();
        __syncthreads();
        if (c < 7) {
            const float* src = A + (size_t)(r0 + ar) * II + (c + 1) * 32 + ac;
            uint32_t d = abuf[(c + 1) & 1] + (ar * PAS + ac) * 4;
            cpa16(d, src); cpa16(d + 16, src + 4);
            cpa16(d + 32, src + 8); cpa16(d + 48, src + 12);
            CPA_COMMIT();
            int WHn = whb[(c + 1) & 1], WLn = wlb[(c + 1) & 1];
            float4 w0 = *(const float4*)(Wh + ((c + 1) * 32 + kr) * DD + c8w);
            float4 w1 = *(const float4*)(Wh + ((c + 1) * 32 + kr) * DD + c8w + 4);
            const float* wf0 = &w0.x; const float* wf1 = &w1.x;
#pragma unroll
            for (int e = 0; e < 4; e++) {
                float v = wf0[e], h = tf32_rn(v);
                sm[WHn + (c8w + e) * WTS + wpos] = h;
                sm[WLn + (c8w + e) * WTS + wpos] = v - h;
                v = wf1[e]; h = tf32_rn(v);
                sm[WHn + (c8w + 4 + e) * WTS + wpos] = h;
                sm[WLn + (c8w + 4 + e) * WTS + wpos] = v - h;
            }
        }
        const int ab = (c & 1) ? P_AB1 : P_AB0;
        const int WHc = whb[c & 1], WLc = wlb[c & 1];
#pragma unroll
        for (int sk = 0; sk < 4; sk++) {
            uint32_t ah[4], al[4];
#pragma unroll
            for (int e = 0; e < 4; e++) {
                int row = R + (e & 1) * 8 + lq;
                int col = sk * 8 + (e >> 1) * 4 + lr;
                float v = sm[ab + row * PAS + col];
                float h = tf32_rn(v);
                ah[e] = __float_as_uint(h);
                al[e] = __float_as_uint(v - h);
            }
#pragma unroll
            for (int nt = 0; nt < 8; nt++) {
                int wa = (nt * 8 + lq) * WTS + sk * 8 + 2 * lr;
                float2 wh2 = *(const float2*)&sm[WHc + wa];
                float2 wl2 = *(const float2*)&sm[WLc + wa];
                mma8f(o[nt], ah, wh2);
                mma8f(o[nt], ah, wl2);
                mma8f(o[nt], al, wh2);
            }
        }
    }

    // ---- epilogue ----
    const int mr0 = r0 + R + lq;
    const int mr1 = mr0 + 8;
    int b0 = mr0 >> 10, g0 = mr0 & (GG - 1);
    int b1 = mr1 >> 10, g1 = mr1 & (GG - 1);
    float* o0 = outbuf + (((size_t)(b0 * HH + hh) * GG + g0) * DD);
    float* o1 = outbuf + (((size_t)(b1 * HH + hh) * GG + g1) * DD);
#pragma unroll
    for (int nt = 0; nt < 8; nt++) {
        *(float2*)&o0[nt * 8 + 2 * lr] = make_float2(o[nt][0], o[nt][1]);
        *(float2*)&o1[nt * 8 + 2 * lr] = make_float2(o[nt][2], o[nt][3]);
    }
}

// ===========================================================================
// Flash attention: S = tf32 QhKh (2 k8 mma / 16k) + bf16 k16 cross terms
// (QlbKhb + QhbKlb). PV = single-term tf32. l summed over rounded P.
// ===========================================================================
#define AKH 0                       // K hi tf32 pair-interleaved: 64*72
#define KHB 4608                    // K hi bf16x2: 64*40
#define KLB 7168                    // K lo bf16x2: 64*40
#define AVH 9728                    // V hi tf32: 64*72
#define ASP 14336                   // P / Q staging: 64*68
#define AMB 18688                   // mask bits: 2048
#define A_SM_WORDS 20736            // 82944 bytes
#define AKS 72
#define KBS 40
#define AVS 72
#define APS 68

__global__ __launch_bounds__(128) void attn_mma_kernel(float* __restrict__ out)
{
    extern __shared__ float sm[];
    uint32_t* smw = (uint32_t*)sm;
    uint32_t* smMB = (uint32_t*)&sm[AMB];

    const int q0  = blockIdx.x * 64;
    const int bh  = blockIdx.y;
    const int tid = threadIdx.x;
    const int lane = tid & 31;
    const int w   = tid >> 5;
    const int lq = lane >> 2;
    const int lr = lane & 3;
    const int R  = w * 16;
    const int mr0 = R + lq;
    const int mr1 = mr0 + 8;

    const float* qb = g_q + (size_t)bh * GG * DD;
    const float* kb = g_k + (size_t)bh * GG * DD;
    const float* vb = g_v + (size_t)bh * GG * DD;

    // ---- stage Q (scaled) into P region, copy mask bits ----
#pragma unroll
    for (int t = 0; t < 8; t++) {
        int id = tid + t * 128;
        int r  = id >> 4;
        int c4 = (id & 15) << 2;
        float4 v = *(const float4*)(qb + (size_t)(q0 + r) * DD + c4);
        v.x *= 0.125f; v.y *= 0.125f; v.z *= 0.125f; v.w *= 0.125f;
        *(float4*)&sm[ASP + r * APS + c4] = v;
    }
#pragma unroll
    for (int t = 0; t < 4; t++) {
        int id = tid + t * 128;
        ((uint4*)smMB)[id] = ((const uint4*)(g_mbits + q0 * 32))[id];
    }
    __syncthreads();

    // ---- Q fragments: tf32 hi (k8) + bf16 hi/lo (k16) ----
    uint32_t qh[8][4];               // tf32 k8 a-frags
    uint32_t qhb[4][4], qlb[4][4];   // bf16 k16 a-frags
#pragma unroll
    for (int sk = 0; sk < 8; sk++)
#pragma unroll
        for (int e = 0; e < 4; e++) {
            int row = R + (e & 1) * 8 + lq;
            int col = sk * 8 + (e >> 1) * 4 + lr;
            float v = sm[ASP + row * APS + col];
            qh[sk][e] = __float_as_uint(tf32_rn(v));
        }
#pragma unroll
    for (int cc = 0; cc < 4; cc++)
#pragma unroll
        for (int e = 0; e < 4; e++) {
            int row = R + (e & 1) * 8 + lq;
            int col = cc * 16 + (e >> 1) * 8 + 2 * lr;
            float2 x = *(const float2*)&sm[ASP + row * APS + col];
            float h0 = tf32_rn(x.x), h1 = tf32_rn(x.y);
            qhb[cc][e] = bf2pack(h0, h1);
            qlb[cc][e] = bf2pack(x.x - h0, x.y - h1);
        }

    float o[8][4];
#pragma unroll
    for (int nt = 0; nt < 8; nt++)
#pragma unroll
        for (int e = 0; e < 4; e++) o[nt][e] = 0.f;
    float m0 = -1e30f, m1 = -1e30f, l0 = 0.f, l1 = 0.f;

    for (int kt = 0; kt < 16; kt++) {
        __syncthreads();
        const float* kbt = kb + (size_t)kt * 64 * DD;
        const float* vbt = vb + (size_t)kt * 64 * DD;
        // K prep: tf32-hi pair-interleaved + bf16 hi/lo k16-interleaved
#pragma unroll
        for (int t = 0; t < 4; t++) {
            int u  = tid + t * 128;
            int j  = u >> 3;
            int c8 = (u & 7) * 8;
            float4 x0 = *(const float4*)(kbt + j * DD + c8);
            float4 x1 = *(const float4*)(kbt + j * DD + c8 + 4);
            float h0 = tf32_rn(x0.x), h1 = tf32_rn(x0.y),
                  h2 = tf32_rn(x0.z), h3 = tf32_rn(x0.w);
            float h4 = tf32_rn(x1.x), h5 = tf32_rn(x1.y),
                  h6 = tf32_rn(x1.z), h7 = tf32_rn(x1.w);
            int ba = AKH + j * AKS + c8;
            *(float4*)&sm[ba]     = make_float4(h0, h4, h1, h5);
            *(float4*)&sm[ba + 4] = make_float4(h2, h6, h3, h7);
            // bf16 tiles: chunk cc = c8/16; word base parity from c8&8
            int cc = c8 >> 4;
            int wb = j * KBS + cc * 8 + ((c8 & 8) ? 1 : 0);
            smw[KHB + wb + 0] = bf2pack(h0, h1);
            smw[KHB + wb + 2] = bf2pack(h2, h3);
            smw[KHB + wb + 4] = bf2pack(h4, h5);
            smw[KHB + wb + 6] = bf2pack(h6, h7);
            smw[KLB + wb + 0] = bf2pack(x0.x - h0, x0.y - h1);
            smw[KLB + wb + 2] = bf2pack(x0.z - h2, x0.w - h3);
            smw[KLB + wb + 4] = bf2pack(x1.x - h4, x1.y - h5);
            smw[KLB + wb + 6] = bf2pack(x1.z - h6, x1.w - h7);
        }
        // V: tf32 hi only, natural layout
#pragma unroll
        for (int t = 0; t < 8; t++) {
            int id = tid + t * 128;
            int j  = id >> 4;
            int c4 = (id & 15) << 2;
            float4 vv = *(const float4*)(vbt + j * DD + c4);
            *(float4*)&sm[AVH + j * AVS + c4] =
                make_float4(tf32_rn(vv.x), tf32_rn(vv.y),
                            tf32_rn(vv.z), tf32_rn(vv.w));
        }
        __syncthreads();

        // ---- S = Q K^T : tf32 main + bf16 cross ----
        float s[8][4];
#pragma unroll
        for (int nt = 0; nt < 8; nt++)
#pragma unroll
            for (int e = 0; e < 4; e++) s[nt][e] = 0.f;

#pragma unroll
        for (int cc = 0; cc < 4; cc++) {
#pragma unroll
            for (int nt = 0; nt < 8; nt++) {
                int row = nt * 8 + lq;
                int ka0 = AKH + row * AKS + (2 * cc) * 8 + 2 * lr;
                float2 b0 = *(const float2*)&sm[ka0];
                float2 b1 = *(const float2*)&sm[ka0 + 8];
                mma8f(s[nt], qh[2 * cc], b0);
                mma8f(s[nt], qh[2 * cc + 1], b1);
                int kbw = row * KBS + cc * 8 + 2 * lr;
                uint2 kh2 = *(const uint2*)&smw[KHB + kbw];
                uint2 kl2 = *(const uint2*)&smw[KLB + kbw];
                mma16b(s[nt], qlb[cc], kh2.x, kh2.y);
                mma16b(s[nt], qhb[cc], kl2.x, kl2.y);
            }
        }

        // ---- mask + online softmax ----
        uint32_t w00 = smMB[mr0 * 32 + 2 * kt], w01 = smMB[mr0 * 32 + 2 * kt + 1];
        uint32_t w10 = smMB[mr1 * 32 + 2 * kt], w11 = smMB[mr1 * 32 + 2 * kt + 1];

        float tm0 = -1e30f, tm1 = -1e30f;
#pragma unroll
        for (int nt = 0; nt < 8; nt++) {
            uint32_t wa = (nt < 4) ? w00 : w01;
            uint32_t wb2 = (nt < 4) ? w10 : w11;
            int sh = 8 * (nt & 3) + 2 * lr;
            uint32_t ma = (wa >> sh) & 3u;
            uint32_t mb = (wb2 >> sh) & 3u;
            s[nt][0] = (ma & 1u) ? -1e30f : s[nt][0];
            s[nt][1] = (ma & 2u) ? -1e30f : s[nt][1];
            s[nt][2] = (mb & 1u) ? -1e30f : s[nt][2];
            s[nt][3] = (mb & 2u) ? -1e30f : s[nt][3];
            tm0 = fmaxf(tm0, fmaxf(s[nt][0], s[nt][1]));
            tm1 = fmaxf(tm1, fmaxf(s[nt][2], s[nt][3]));
        }
        tm0 = fmaxf(tm0, __shfl_xor_sync(0xffffffffu, tm0, 1));
        tm0 = fmaxf(tm0, __shfl_xor_sync(0xffffffffu, tm0, 2));
        tm1 = fmaxf(tm1, __shfl_xor_sync(0xffffffffu, tm1, 1));
        tm1 = fmaxf(tm1, __shfl_xor_sync(0xffffffffu, tm1, 2));

        float mn0 = fmaxf(m0, tm0), mn1 = fmaxf(m1, tm1);
        float a0 = __expf(m0 - mn0), a1 = __expf(m1 - mn1);
        m0 = mn0; m1 = mn1;

        float rs0 = 0.f, rs1 = 0.f;
#pragma unroll
        for (int nt = 0; nt < 8; nt++) {
            float p0 = tf32_rn(__expf(s[nt][0] - mn0));
            float p1 = tf32_rn(__expf(s[nt][1] - mn0));
            float p2 = tf32_rn(__expf(s[nt][2] - mn1));
            float p3 = tf32_rn(__expf(s[nt][3] - mn1));
            rs0 += p0 + p1;
            rs1 += p2 + p3;
            *(float2*)&sm[ASP + mr0 * APS + nt * 8 + 2 * lr] = make_float2(p0, p1);
            *(float2*)&sm[ASP + mr1 * APS + nt * 8 + 2 * lr] = make_float2(p2, p3);
        }
        rs0 += __shfl_xor_sync(0xffffffffu, rs0, 1);
        rs0 += __shfl_xor_sync(0xffffffffu, rs0, 2);
        rs1 += __shfl_xor_sync(0xffffffffu, rs1, 1);
        rs1 += __shfl_xor_sync(0xffffffffu, rs1, 2);
        l0 = l0 * a0 + rs0;
        l1 = l1 * a1 + rs1;
#pragma unroll
        for (int nt = 0; nt < 8; nt++) {
            o[nt][0] *= a0; o[nt][1] *= a0;
            o[nt][2] *= a1; o[nt][3] *= a1;
        }
        __syncwarp();

        // ---- O += P V (single-term tf32) ----
#pragma unroll
        for (int u = 0; u < 8; u++) {
            uint32_t pa[4];
            pa[0] = __float_as_uint(sm[ASP + mr0 * APS + u * 8 + lr]);
            pa[1] = __float_as_uint(sm[ASP + mr1 * APS + u * 8 + lr]);
            pa[2] = __float_as_uint(sm[ASP + mr0 * APS + u * 8 + 4 + lr]);
            pa[3] = __float_as_uint(sm[ASP + mr1 * APS + u * 8 + 4 + lr]);
#pragma unroll
            for (int nt = 0; nt < 8; nt++) {
                int va = AVH + (u * 8 + lr) * AVS + nt * 8 + lq;
                uint32_t vh0 = __float_as_uint(sm[va]);
                uint32_t vh1 = __float_as_uint(sm[va + 4 * AVS]);
                mma8(o[nt], pa, vh0, vh1);
            }
        }
    }

    // ---- epilogue ----
    float i0 = 1.f / l0, i1 = 1.f / l1;
    float* ob = out + ((size_t)bh * GG + q0) * DD;
#pragma unroll
    for (int nt = 0; nt < 8; nt++) {
        *(float2*)&ob[(size_t)mr0 * DD + nt * 8 + 2 * lr] =
            make_float2(o[nt][0] * i0, o[nt][1] * i0);
        *(float2*)&ob[(size_t)mr1 * DD + nt * 8 + 2 * lr] =
            make_float2(o[nt][2] * i1, o[nt][3] * i1);
    }
}

// ---------------------------------------------------------------------------
extern "C" void kernel_launch(void* const* d_in, const int* in_sizes, int n_in,
                              void* d_out, int out_size)
{
    const float* h    = (const float*)d_in[0];
    const int*   mask = (const int*)  d_in[1];
    const float* W_Q  = (const float*)d_in[2];
    const float* W_K  = (const float*)d_in[3];
    const float* W_V  = (const float*)d_in[4];
    float* out = (float*)d_out;

    cudaFuncSetAttribute(proj_mma_kernel,
                         cudaFuncAttributeMaxDynamicSharedMemorySize,
                         P_SM_WORDS * 4);
    cudaFuncSetAttribute(attn_mma_kernel,
                         cudaFuncAttributeMaxDynamicSharedMemorySize,
                         A_SM_WORDS * 4);

    dim3 pgrid(128, 8, 3);
    proj_mma_kernel<<<pgrid, 256, P_SM_WORDS * 4>>>(h, W_Q, W_K, W_V);

    maskpack_kernel<<<128, 256>>>(mask);

    dim3 agrid(GG / 64, BB * HH);
    attn_mma_kernel<<<agrid, 128, A_SM_WORDS * 4>>>(out);
}